// round 1
// baseline (speedup 1.0000x reference)
#include <cuda_runtime.h>
#include <math.h>

#define NPTS 4096
#define BATCH 4
#define CCH 128
#define KNN 10

// ---------------- scratch (device globals: allocation-free) ----------------
__device__ float g_Wc1[256 * 128];              // [(A1-B1); B1]  (256 x 128)
__device__ float g_Wc2[512 * 128];              // [(A2-B2); B2]  (512 x 128)
__device__ float g_UV1[BATCH * 256 * NPTS];     // U1 rows 0..127, V1 rows 128..255
__device__ float g_UV2[BATCH * 512 * NPTS];     // U2 rows 0..255, V2 rows 256..511
__device__ float g_xcat[BATCH * 512 * NPTS];    // rows 0..127 x0 | 128..255 x1 | 256..511 x2
__device__ float g_y3[BATCH * CCH * NPTS];
__device__ int   g_idx[BATCH * NPTS * KNN];

// ---------------- weight prep: split + combine halves ----------------
__global__ void prep_w(const float* __restrict__ W1, const float* __restrict__ W2,
                       float* __restrict__ Wc1, float* __restrict__ Wc2) {
    int i = blockIdx.x * blockDim.x + threadIdx.x;
    if (i < 256 * 128) {                // Wc1: 256 x 128
        int o = i / 128, c = i % 128;
        if (o < 128) Wc1[i] = W1[o * 256 + c] - W1[o * 256 + 128 + c];
        else         Wc1[i] = W1[(o - 128) * 256 + 128 + c];
    }
    if (i < 512 * 128) {                // Wc2: 512 x 128
        int o = i / 128, c = i % 128;
        if (o < 256) Wc2[i] = W2[o * 256 + c] - W2[o * 256 + 128 + c];
        else         Wc2[i] = W2[(o - 256) * 256 + 128 + c];
    }
}

// ---------------- copy x0 (features) into xcat rows [0,128) ----------------
__global__ void copy_x0(const float4* __restrict__ f, float4* __restrict__ xcat) {
    int i = blockIdx.x * blockDim.x + threadIdx.x;
    const int per = CCH * NPTS / 4;            // 131072 float4 per batch
    if (i >= BATCH * per) return;
    int b = i / per, r = i % per;
    xcat[(size_t)b * (512 * NPTS / 4) + r] = f[i];
}

// ---------------- KNN: top-10 nearest (excl. self), insertion list ----------------
__global__ void knn_kernel(const float* __restrict__ coords, int* __restrict__ out_idx) {
    int b = blockIdx.y;
    int n = blockIdx.x * blockDim.x + threadIdx.x;
    const float* cb = coords + (size_t)b * 3 * NPTS;
    __shared__ float sx[1024], sy[1024], sz[1024], ss[1024];

    float qx = cb[n], qy = cb[NPTS + n], qz = cb[2 * NPTS + n];
    float qs = qx * qx + qy * qy + qz * qz;

    float dist[KNN];
    int   ind[KNN];
#pragma unroll
    for (int i = 0; i < KNN; i++) { dist[i] = 3.4e38f; ind[i] = 0; }
    float worst = 3.4e38f;

    for (int t = 0; t < NPTS; t += 1024) {
        __syncthreads();
        for (int j = threadIdx.x; j < 1024; j += blockDim.x) {
            float x = cb[t + j], y = cb[NPTS + t + j], z = cb[2 * NPTS + t + j];
            sx[j] = x; sy[j] = y; sz[j] = z; ss[j] = x * x + y * y + z * z;
        }
        __syncthreads();
        for (int j = 0; j < 1024; j++) {
            int jj = t + j;
            float d = qs + ss[j] - 2.f * (qx * sx[j] + qy * sy[j] + qz * sz[j]);
            d = fmaxf(d, 1e-12f);
            if (d < worst && jj != n) {
                int p = KNN - 1;
                while (p > 0 && dist[p - 1] > d) {
                    dist[p] = dist[p - 1]; ind[p] = ind[p - 1]; p--;
                }
                dist[p] = d; ind[p] = jj;
                worst = dist[KNN - 1];
            }
        }
    }
    int* op = out_idx + ((size_t)b * NPTS + n) * KNN;
#pragma unroll
    for (int i = 0; i < KNN; i++) op[i] = ind[i];
}

// ---------------- fp32 tiled GEMM:  O[b] = A (MxK) * X[b] (K x 4096) ----------------
// grid: (4096/64, M/64, BATCH), block: 256 threads, 4x4 microtile.
__global__ void gemm_kernel(const float* __restrict__ A, const float* __restrict__ X,
                            float* __restrict__ O, int Kd,
                            size_t strideX, size_t strideO) {
    const int NN = NPTS;
    int b = blockIdx.z;
    const float* Xb = X + (size_t)b * strideX;
    float* Ob = O + (size_t)b * strideO;
    int n0 = blockIdx.x * 64, m0 = blockIdx.y * 64;

    __shared__ float As[16][68];   // padded; 68*4 B = 272 B (16B-aligned rows)
    __shared__ float Xs[16][64];

    int tid = threadIdx.x;
    int tn = (tid & 15) * 4;
    int tm = (tid >> 4) * 4;
    float acc[4][4] = {};

    for (int k0 = 0; k0 < Kd; k0 += 16) {
        {   // A tile: 64(m) x 16(k); each thread loads 4 consecutive k
            int mm = tid >> 2;
            int kk = (tid & 3) * 4;
            float4 v = *(const float4*)&A[(size_t)(m0 + mm) * Kd + k0 + kk];
            As[kk + 0][mm] = v.x; As[kk + 1][mm] = v.y;
            As[kk + 2][mm] = v.z; As[kk + 3][mm] = v.w;
        }
        {   // X tile: 16(k) x 64(n), coalesced float4
            int kk = tid >> 4;
            int nn = (tid & 15) * 4;
            *(float4*)&Xs[kk][nn] =
                *(const float4*)&Xb[(size_t)(k0 + kk) * NN + n0 + nn];
        }
        __syncthreads();
#pragma unroll
        for (int kk = 0; kk < 16; kk++) {
            float4 a = *(const float4*)&As[kk][tm];
            float4 x = *(const float4*)&Xs[kk][tn];
            float av[4] = {a.x, a.y, a.z, a.w};
            float xv[4] = {x.x, x.y, x.z, x.w};
#pragma unroll
            for (int i = 0; i < 4; i++)
#pragma unroll
                for (int j = 0; j < 4; j++)
                    acc[i][j] += av[i] * xv[j];
        }
        __syncthreads();
    }
#pragma unroll
    for (int i = 0; i < 4; i++) {
        float4 v = make_float4(acc[i][0], acc[i][1], acc[i][2], acc[i][3]);
        *(float4*)&Ob[(size_t)(m0 + tm + i) * NN + n0 + tn] = v;
    }
}

// ---------------- EdgeConv epilogue: gather, stats over (N,k), max_k, norm, lrelu ----------------
// One block per (channel o, batch b).
__global__ void edge_epilogue(const float* __restrict__ UV, const int* __restrict__ idx,
                              float* __restrict__ xcat, int Ch, int rowsPerBatch, int outRow0) {
    int o = blockIdx.x, b = blockIdx.y, tid = threadIdx.x;
    const float* U = UV + ((size_t)b * rowsPerBatch + o) * NPTS;
    const float* V = UV + ((size_t)b * rowsPerBatch + Ch + o) * NPTS;
    const int* id = idx + (size_t)b * NPTS * KNN;
    float* op = xcat + ((size_t)b * 512 + outRow0 + o) * NPTS;

    __shared__ float  smax[NPTS];
    __shared__ double sred[256], s2red[256];
    __shared__ float  smu, srstd;

    double s = 0.0, s2 = 0.0;
    for (int n = tid; n < NPTS; n += 256) {
        float u = U[n];
        float m = -3.4e38f;
#pragma unroll
        for (int kk = 0; kk < KNN; kk++) {
            float v = V[id[n * KNN + kk]];
            float y = u + v;
            s  += (double)y;
            s2 += (double)y * (double)y;
            m = fmaxf(m, y);
        }
        smax[n] = m;
    }
    sred[tid] = s; s2red[tid] = s2;
    __syncthreads();
    for (int st = 128; st > 0; st >>= 1) {
        if (tid < st) { sred[tid] += sred[tid + st]; s2red[tid] += s2red[tid + st]; }
        __syncthreads();
    }
    if (tid == 0) {
        double cnt = (double)NPTS * KNN;
        double mu  = sred[0] / cnt;
        double var = s2red[0] / cnt - mu * mu;
        smu   = (float)mu;
        srstd = (float)(1.0 / sqrt(var + 1e-5));
    }
    __syncthreads();
    float mu = smu, r = srstd;
    for (int n = tid; n < NPTS; n += 256) {
        float v = (smax[n] - mu) * r;
        op[n] = v >= 0.f ? v : 0.2f * v;
    }
}

// ---------------- final instance-norm (over N) + lrelu ----------------
__global__ void norm_epilogue(const float* __restrict__ Y, float* __restrict__ out) {
    int o = blockIdx.x, b = blockIdx.y, tid = threadIdx.x;
    const float* y = Y + ((size_t)b * CCH + o) * NPTS;
    float* op = out + ((size_t)b * CCH + o) * NPTS;

    __shared__ double sred[256], s2red[256];
    __shared__ float  smu, srstd;

    double s = 0.0, s2 = 0.0;
    for (int n = tid; n < NPTS; n += 256) {
        float v = y[n];
        s += (double)v; s2 += (double)v * (double)v;
    }
    sred[tid] = s; s2red[tid] = s2;
    __syncthreads();
    for (int st = 128; st > 0; st >>= 1) {
        if (tid < st) { sred[tid] += sred[tid + st]; s2red[tid] += s2red[tid + st]; }
        __syncthreads();
    }
    if (tid == 0) {
        double cnt = (double)NPTS;
        double mu  = sred[0] / cnt;
        double var = s2red[0] / cnt - mu * mu;
        smu   = (float)mu;
        srstd = (float)(1.0 / sqrt(var + 1e-5));
    }
    __syncthreads();
    float mu = smu, r = srstd;
    for (int n = tid; n < NPTS; n += 256) {
        float v = (y[n] - mu) * r;
        op[n] = v >= 0.f ? v : 0.2f * v;
    }
}

// ---------------- launch ----------------
extern "C" void kernel_launch(void* const* d_in, const int* in_sizes, int n_in,
                              void* d_out, int out_size) {
    const float* coords = (const float*)d_in[0];   // [4,3,4096]
    const float* feats  = (const float*)d_in[1];   // [4,128,4096]
    const float* W1     = (const float*)d_in[2];   // [128,256]
    const float* W2     = (const float*)d_in[3];   // [256,256]
    const float* W3     = (const float*)d_in[4];   // [128,512]
    float* out = (float*)d_out;                    // [4,128,4096]

    float *Wc1, *Wc2, *UV1, *UV2, *xcat, *y3;
    int* idx;
    cudaGetSymbolAddress((void**)&Wc1,  g_Wc1);
    cudaGetSymbolAddress((void**)&Wc2,  g_Wc2);
    cudaGetSymbolAddress((void**)&UV1,  g_UV1);
    cudaGetSymbolAddress((void**)&UV2,  g_UV2);
    cudaGetSymbolAddress((void**)&xcat, g_xcat);
    cudaGetSymbolAddress((void**)&y3,   g_y3);
    cudaGetSymbolAddress((void**)&idx,  g_idx);

    // weight prep + x0 copy + knn (independent of each other, sequential is fine)
    prep_w<<<256, 256>>>(W1, W2, Wc1, Wc2);
    copy_x0<<<(BATCH * CCH * NPTS / 4 + 255) / 256, 256>>>((const float4*)feats, (float4*)xcat);
    knn_kernel<<<dim3(NPTS / 256, BATCH), 256>>>(coords, idx);

    // stage 1: UV1 = Wc1 @ x0
    gemm_kernel<<<dim3(NPTS / 64, 256 / 64, BATCH), 256>>>(
        Wc1, xcat, UV1, 128, (size_t)512 * NPTS, (size_t)256 * NPTS);
    edge_epilogue<<<dim3(128, BATCH), 256>>>(UV1, idx, xcat, 128, 256, 128);

    // stage 2: UV2 = Wc2 @ x1
    gemm_kernel<<<dim3(NPTS / 64, 512 / 64, BATCH), 256>>>(
        Wc2, xcat + (size_t)128 * NPTS, UV2, 128, (size_t)512 * NPTS, (size_t)512 * NPTS);
    edge_epilogue<<<dim3(256, BATCH), 256>>>(UV2, idx, xcat, 256, 512, 256);

    // stage 3: y3 = W3 @ [x0;x1;x2]
    gemm_kernel<<<dim3(NPTS / 64, 128 / 64, BATCH), 256>>>(
        W3, xcat, y3, 512, (size_t)512 * NPTS, (size_t)128 * NPTS);
    norm_epilogue<<<dim3(128, BATCH), 256>>>(y3, out);
}